// round 11
// baseline (speedup 1.0000x reference)
#include <cuda_runtime.h>
#include <cstdint>

#define D 96
#define MAX_N 50000
#define MAXDEG 64
#define MAX_OVF 4096

// ---- scratch (static device globals; no allocation) -----------------------
__device__ uint32_t g_wt[D * D];                // tf32-rounded W bits
__device__ int      g_cnt[MAX_N];               // per-node cursor / degree
__device__ int2     g_pack[MAX_N * MAXDEG];     // (src, bitcast(w)) buckets
__device__ int      g_ovfcnt;
__device__ int4     g_ovf[MAX_OVF];             // (src, dst, bitcast(w), pad)
__device__ int      g_done;                     // grid ticket for ovf reset

__device__ __forceinline__ uint32_t smem_u32(const void* p) {
    uint32_t a;
    asm("{ .reg .u64 t; cvta.to.shared.u64 t, %1; cvt.u32.u64 %0, t; }"
        : "=r"(a) : "l"(p));
    return a;
}
__device__ __forceinline__ uint32_t tf32_bits(float x) {
    uint32_t u;
    asm("cvt.rna.tf32.f32 %0, %1;" : "=r"(u) : "f"(x));
    return u;
}

// ---------------------------------------------------------------------------
// K1: bucket edges (EPT=2, max TLP for the atomic-latency-bound path).
// First 36 blocks additionally pre-convert W to tf32 bits (9216 elements).
// g_cnt is zero on entry: zero-init at module load, then self-cleaned by the
// fused kernel each run.
// ---------------------------------------------------------------------------
#define EPT 2
__global__ void bucket_kernel(const int* __restrict__ ei,
                              const float* __restrict__ ew,
                              const float* __restrict__ pr,
                              const float* __restrict__ Wm,
                              int E) {
    if (blockIdx.x < (D * D + 255) / 256) {
        int i = blockIdx.x * 256 + threadIdx.x;
        if (i < D * D) g_wt[i] = tf32_bits(__ldg(Wm + i));
    }

    int base = (blockIdx.x * blockDim.x + threadIdx.x) * EPT;
    int src[EPT], dst[EPT];
    float w[EPT];
#pragma unroll
    for (int u = 0; u < EPT; u++) {
        int e = base + u;
        if (e < E) { src[u] = __ldg(ei + e); dst[u] = __ldg(ei + E + e); w[u] = __ldg(ew + e); }
    }
#pragma unroll
    for (int u = 0; u < EPT; u++) {
        int e = base + u;
        if (e < E) w[u] *= __ldg(pr + src[u]);
    }
#pragma unroll
    for (int u = 0; u < EPT; u++) {
        int e = base + u;
        if (e < E) {
            int pos = atomicAdd(&g_cnt[dst[u]], 1);
            if (pos < MAXDEG) {
                g_pack[dst[u] * MAXDEG + pos] = make_int2(src[u], __float_as_int(w[u]));
            } else {
                int o = atomicAdd(&g_ovfcnt, 1);
                if (o < MAX_OVF)
                    g_ovf[o] = make_int4(src[u], dst[u], __float_as_int(w[u]), 0);
            }
        }
    }
}

// ---------------------------------------------------------------------------
// K2: FUSED aggregate + tf32 mma.sync GEMM.
// Per CTA (256 thr): 128-node tile.
//  Phase A: cp.async W tile fill (overlaps with phase B).
//  Phase B: warp w aggregates nodes w*16..w*16+15 (residual +x folded,
//           unroll-4 gathers, self-clean g_cnt) -> tf32 rows STS'd into sA.
//  Phase C: 8 warps = 4 M x 2 N groups, warp tile 2 m16 x 6 n8, 12 K-steps.
// smem pad LDP=100 keeps every LDS/STS conflict-free.
// Grid ticket: last CTA resets g_ovfcnt/g_done for the next replay.
// ---------------------------------------------------------------------------
#define LDP 100
#define NTILE 128
__global__ __launch_bounds__(256, 2)
void fused_kernel(const float* __restrict__ x,
                  const float* __restrict__ bias,
                  float* __restrict__ out,
                  int N) {
    extern __shared__ uint32_t smem[];
    uint32_t* sA = smem;                 // [128][LDP] tf32 node tile
    uint32_t* sW = smem + NTILE * LDP;   // [96][LDP]  tf32 weights
    uint32_t sW_b = smem_u32(sW);

    int t   = threadIdx.x;               // 0..255
    int lid = t & 31;
    int wid = t >> 5;                    // 0..7
    int row0 = blockIdx.x * NTILE;

    // ---- Phase A: async W fill (completes under phase B) ----
    for (int i = t; i < D * (D / 4); i += 256) {
        int r = i / (D / 4), c4 = i % (D / 4);
        const uint32_t* src = g_wt + (size_t)r * D + c4 * 4;
        uint32_t dstp = sW_b + (uint32_t)(r * LDP + c4 * 4) * 4u;
        asm volatile("cp.async.cg.shared.global [%0], [%1], 16;"
                     :: "r"(dstp), "l"(src));
    }
    asm volatile("cp.async.commit_group;");

    // ---- Phase B: aggregation, 16 nodes per warp ----
    int ovf = g_ovfcnt;
    if (ovf > MAX_OVF) ovf = MAX_OVF;

    for (int nn = 0; nn < 16; nn++) {
        int node = row0 + wid * 16 + nn;
        float a0 = 0.f, a1 = 0.f, a2 = 0.f;

        if (node < N) {
            int cnt = g_cnt[node];
            if (cnt > MAXDEG) cnt = MAXDEG;

            const int2* bucket = g_pack + (size_t)node * MAXDEG;
            const float* xr0 = x + (size_t)node * D;
            a0 = __ldg(xr0 + lid);
            a1 = __ldg(xr0 + 32 + lid);
            a2 = __ldg(xr0 + 64 + lid);

            int j = 0;
            for (; j + 4 <= cnt; j += 4) {
                int   s[4]; float w[4];
#pragma unroll
                for (int u = 0; u < 4; u++) {
                    int2 p = __ldg(bucket + j + u);   // uniform addr broadcast
                    s[u] = p.x; w[u] = __int_as_float(p.y);
                }
                float b0[4], b1[4], b2[4];
#pragma unroll
                for (int u = 0; u < 4; u++) {
                    const float* xr = x + (size_t)s[u] * D;
                    b0[u] = __ldg(xr + lid);
                    b1[u] = __ldg(xr + 32 + lid);
                    b2[u] = __ldg(xr + 64 + lid);
                }
#pragma unroll
                for (int u = 0; u < 4; u++) {
                    a0 += w[u] * b0[u];
                    a1 += w[u] * b1[u];
                    a2 += w[u] * b2[u];
                }
            }
            for (; j < cnt; j++) {
                int2 p = __ldg(bucket + j);
                float w = __int_as_float(p.y);
                const float* xr = x + (size_t)p.x * D;
                a0 += w * __ldg(xr + lid);
                a1 += w * __ldg(xr + 32 + lid);
                a2 += w * __ldg(xr + 64 + lid);
            }

            if (ovf > 0) {
                for (int i = 0; i < ovf; i++) {
                    int4 p = g_ovf[i];
                    if (p.y == node) {
                        float w = __int_as_float(p.z);
                        const float* xr = x + (size_t)p.x * D;
                        a0 += w * __ldg(xr + lid);
                        a1 += w * __ldg(xr + 32 + lid);
                        a2 += w * __ldg(xr + 64 + lid);
                    }
                }
            }

            if (lid == 0) g_cnt[node] = 0;         // self-clean for next run
        }

        uint32_t* rp = sA + (wid * 16 + nn) * LDP; // bank l -> conflict-free
        rp[lid]      = tf32_bits(a0);
        rp[32 + lid] = tf32_bits(a1);
        rp[64 + lid] = tf32_bits(a2);
    }

    asm volatile("cp.async.wait_group 0;");
    __syncthreads();

    // grid ticket: last CTA resets ovf state (all CTAs have read g_ovfcnt)
    if (t == 0) {
        __threadfence();
        if (atomicAdd(&g_done, 1) == gridDim.x - 1) {
            g_ovfcnt = 0;
            g_done = 0;
            __threadfence();
        }
    }

    // ---- Phase C: mma mainloop ----
    int m0 = (wid & 3) * 32;
    int n0 = (wid >> 2) * 48;
    int arow = lid >> 2;                 // 0..7
    int acol = lid & 3;                  // 0..3

    float c[2][6][4];
#pragma unroll
    for (int mt = 0; mt < 2; mt++)
#pragma unroll
        for (int nt = 0; nt < 6; nt++)
#pragma unroll
            for (int q = 0; q < 4; q++) c[mt][nt][q] = 0.f;

#pragma unroll
    for (int ks = 0; ks < 12; ks++) {
        int k0 = ks * 8;

        uint32_t a[2][4];
#pragma unroll
        for (int mt = 0; mt < 2; mt++) {
            const uint32_t* base = sA + (m0 + mt * 16 + arow) * LDP + k0 + acol;
            a[mt][0] = base[0];
            a[mt][1] = base[8 * LDP];
            a[mt][2] = base[4];
            a[mt][3] = base[8 * LDP + 4];
        }
        uint32_t bfr[6][2];
#pragma unroll
        for (int nt = 0; nt < 6; nt++) {
            const uint32_t* base = sW + (n0 + nt * 8 + arow) * LDP + k0 + acol;
            bfr[nt][0] = base[0];
            bfr[nt][1] = base[4];
        }

#pragma unroll
        for (int mt = 0; mt < 2; mt++)
#pragma unroll
            for (int nt = 0; nt < 6; nt++) {
                asm volatile(
                    "mma.sync.aligned.m16n8k8.row.col.f32.tf32.tf32.f32 "
                    "{%0,%1,%2,%3}, {%4,%5,%6,%7}, {%8,%9}, {%0,%1,%2,%3};"
                    : "+f"(c[mt][nt][0]), "+f"(c[mt][nt][1]),
                      "+f"(c[mt][nt][2]), "+f"(c[mt][nt][3])
                    : "r"(a[mt][0]), "r"(a[mt][1]), "r"(a[mt][2]), "r"(a[mt][3]),
                      "r"(bfr[nt][0]), "r"(bfr[nt][1]));
            }
    }

    // epilogue: c0,c1 -> (row, 2c),(row, 2c+1); c2,c3 -> row+8
#pragma unroll
    for (int nt = 0; nt < 6; nt++) {
        int col = n0 + nt * 8 + 2 * acol;
        float b0 = __ldg(bias + col);
        float b1 = __ldg(bias + col + 1);
#pragma unroll
        for (int mt = 0; mt < 2; mt++) {
            int r_lo = row0 + m0 + mt * 16 + arow;
            if (r_lo < N) {
                float2 v = make_float2(c[mt][nt][0] + b0, c[mt][nt][1] + b1);
                *reinterpret_cast<float2*>(out + (size_t)r_lo * D + col) = v;
            }
            int r_hi = r_lo + 8;
            if (r_hi < N) {
                float2 v = make_float2(c[mt][nt][2] + b0, c[mt][nt][3] + b1);
                *reinterpret_cast<float2*>(out + (size_t)r_hi * D + col) = v;
            }
        }
    }
}

// ---------------------------------------------------------------------------
// Launch. Inputs: x[N*D] f32, edge_index[2*E] i32, edge_weight[E] f32,
//                 pagerank[N] f32, W[D*D] f32, b[D] f32. Output f32 [N,D].
// ---------------------------------------------------------------------------
extern "C" void kernel_launch(void* const* d_in, const int* in_sizes, int n_in,
                              void* d_out, int out_size) {
    const float* x  = (const float*)d_in[0];
    const int*   ei = (const int*)  d_in[1];
    const float* ew = (const float*)d_in[2];
    const float* pr = (const float*)d_in[3];
    const float* Wm = (const float*)d_in[4];
    const float* b  = (const float*)d_in[5];
    float* out = (float*)d_out;

    int N = in_sizes[0] / D;
    int E = in_sizes[1] / 2;

    const int fused_smem = (NTILE * LDP + D * LDP) * (int)sizeof(uint32_t);
    cudaFuncSetAttribute(fused_kernel,
                         cudaFuncAttributeMaxDynamicSharedMemorySize, fused_smem);

    int nthread = (E + EPT - 1) / EPT;
    bucket_kernel<<<(nthread + 255) / 256, 256>>>(ei, ew, pr, Wm, E);

    fused_kernel<<<(N + NTILE - 1) / NTILE, 256, fused_smem>>>(x, b, out, N);
}

// round 12
// speedup vs baseline: 1.3676x; 1.3676x over previous
#include <cuda_runtime.h>
#include <cstdint>

#define D 96
#define MAX_N 50000
#define MAXDEG 64
#define MAX_OVF 4096

// ---- scratch (static device globals; no allocation) -----------------------
__device__ float    g_aggr[MAX_N * D];          // tf32-rounded aggr + x
__device__ uint32_t g_wt[D * D];                // tf32-rounded W bits
__device__ int      g_cnt[MAX_N];               // per-node cursor / degree
__device__ int2     g_pack[MAX_N * MAXDEG];     // (src, bitcast(w)) buckets
__device__ int      g_ovfcnt;
__device__ int4     g_ovf[MAX_OVF];             // (src, dst, bitcast(w), pad)
__device__ int      g_done;                     // warp ticket for ovf reset

__device__ __forceinline__ float to_tf32(float x) {
    float r;
    asm("cvt.rna.tf32.f32 %0, %1;" : "=f"(r) : "f"(x));
    return r;
}
__device__ __forceinline__ uint32_t tf32_bits(float x) {
    uint32_t u;
    asm("cvt.rna.tf32.f32 %0, %1;" : "=r"(u) : "f"(x));
    return u;
}
__device__ __forceinline__ uint32_t smem_u32(const void* p) {
    uint32_t a;
    asm("{ .reg .u64 t; cvta.to.shared.u64 t, %1; cvt.u32.u64 %0, t; }"
        : "=r"(a) : "l"(p));
    return a;
}

// ---------------------------------------------------------------------------
// K1: bucket edges (EPT=4, best measured). First 36 blocks also pre-convert
// W to tf32 bits. g_cnt is zero on entry (module-load zero-init, then
// self-cleaned by the aggregate kernel every run).
// ---------------------------------------------------------------------------
#define EPT 4
__global__ void bucket_kernel(const int* __restrict__ ei,
                              const float* __restrict__ ew,
                              const float* __restrict__ pr,
                              const float* __restrict__ Wm,
                              int E) {
    if (blockIdx.x < (D * D + 255) / 256) {
        int i = blockIdx.x * 256 + threadIdx.x;
        if (i < D * D) g_wt[i] = tf32_bits(__ldg(Wm + i));
    }

    int base = (blockIdx.x * blockDim.x + threadIdx.x) * EPT;
    int src[EPT], dst[EPT];
    float w[EPT];
#pragma unroll
    for (int u = 0; u < EPT; u++) {
        int e = base + u;
        if (e < E) { src[u] = __ldg(ei + e); dst[u] = __ldg(ei + E + e); w[u] = __ldg(ew + e); }
    }
#pragma unroll
    for (int u = 0; u < EPT; u++) {
        int e = base + u;
        if (e < E) w[u] *= __ldg(pr + src[u]);
    }
#pragma unroll
    for (int u = 0; u < EPT; u++) {
        int e = base + u;
        if (e < E) {
            int pos = atomicAdd(&g_cnt[dst[u]], 1);
            if (pos < MAXDEG) {
                g_pack[dst[u] * MAXDEG + pos] = make_int2(src[u], __float_as_int(w[u]));
            } else {
                int o = atomicAdd(&g_ovfcnt, 1);
                if (o < MAX_OVF)
                    g_ovf[o] = make_int4(src[u], dst[u], __float_as_int(w[u]), 0);
            }
        }
    }
}

// ---------------------------------------------------------------------------
// K2: per-node aggregation (R8 structure: high occupancy, smem staging,
// unroll-4 gathers, residual +x folded, tf32-rounded output).
// Self-cleans g_cnt; per-warp grid ticket resets g_ovfcnt/g_done at the end.
// ---------------------------------------------------------------------------
__global__ void aggregate_kernel(const float* __restrict__ x, int N,
                                 int total_warps) {
    __shared__ int2 s_pack[8][MAXDEG];

    int wid  = threadIdx.x >> 5;
    int l    = threadIdx.x & 31;
    int node = blockIdx.x * 8 + wid;

    int ovf = g_ovfcnt;
    if (ovf > MAX_OVF) ovf = MAX_OVF;

    if (node < N) {
        int cnt = g_cnt[node];
        if (cnt > MAXDEG) cnt = MAXDEG;

        const int2* bucket = g_pack + (size_t)node * MAXDEG;
        for (int k = l; k < cnt; k += 32)
            s_pack[wid][k] = __ldg(bucket + k);
        __syncwarp();

        const float* xr0 = x + (size_t)node * D;
        float a0 = __ldg(xr0 + l);
        float a1 = __ldg(xr0 + 32 + l);
        float a2 = __ldg(xr0 + 64 + l);

        int j = 0;
        for (; j + 4 <= cnt; j += 4) {
            int   s[4]; float w[4];
#pragma unroll
            for (int u = 0; u < 4; u++) {
                int2 p = s_pack[wid][j + u];
                s[u] = p.x; w[u] = __int_as_float(p.y);
            }
            float b0[4], b1[4], b2[4];
#pragma unroll
            for (int u = 0; u < 4; u++) {
                const float* xr = x + (size_t)s[u] * D;
                b0[u] = __ldg(xr + l);
                b1[u] = __ldg(xr + 32 + l);
                b2[u] = __ldg(xr + 64 + l);
            }
#pragma unroll
            for (int u = 0; u < 4; u++) {
                a0 += w[u] * b0[u];
                a1 += w[u] * b1[u];
                a2 += w[u] * b2[u];
            }
        }
        for (; j < cnt; j++) {
            int2 p = s_pack[wid][j];
            float w = __int_as_float(p.y);
            const float* xr = x + (size_t)p.x * D;
            a0 += w * __ldg(xr + l);
            a1 += w * __ldg(xr + 32 + l);
            a2 += w * __ldg(xr + 64 + l);
        }

        if (ovf > 0) {
            for (int i = 0; i < ovf; i++) {
                int4 p = g_ovf[i];
                if (p.y == node) {
                    float w = __int_as_float(p.z);
                    const float* xr = x + (size_t)p.x * D;
                    a0 += w * __ldg(xr + l);
                    a1 += w * __ldg(xr + 32 + l);
                    a2 += w * __ldg(xr + 64 + l);
                }
            }
        }

        float* o = g_aggr + (size_t)node * D;
        o[l]      = to_tf32(a0);
        o[32 + l] = to_tf32(a1);
        o[64 + l] = to_tf32(a2);
    }

    // self-clean + per-warp ticket (after this warp's g_ovf reads)
    if (l == 0) {
        if (node < N) g_cnt[node] = 0;
        __threadfence();
        if (atomicAdd(&g_done, 1) == total_warps - 1) {
            g_ovfcnt = 0;
            g_done = 0;
        }
    }
}

// ---------------------------------------------------------------------------
// K3: tf32 mma.sync GEMM. NTILE=64 -> smem 64KB -> 3 CTAs/SM (was 2).
// 8 warps = 2 M-groups (32 rows) x 4 N-groups (24 cols);
// warp tile 2 m16 x 3 n8, K=8/mma, 12 K-steps.
// Fills are cp.async.cg 16B copies (g_aggr / g_wt pre-rounded tf32);
// out-of-range rows zero-filled via src-size=0.
// smem pad 100 floats/row keeps all fragment LDS conflict-free.
// ---------------------------------------------------------------------------
#define LDP 100
#define NTILE 64
__global__ __launch_bounds__(256, 3)
void mma_gemm_kernel(const float* __restrict__ bias,
                     float* __restrict__ out,
                     int N) {
    extern __shared__ uint32_t smem[];
    uint32_t* sA = smem;                 // [64][LDP]
    uint32_t* sW = smem + NTILE * LDP;   // [96][LDP]
    uint32_t sA_b = smem_u32(sA);
    uint32_t sW_b = smem_u32(sW);

    int t   = threadIdx.x;               // 0..255
    int lid = t & 31;
    int wid = t >> 5;                    // 0..7
    int m0  = (wid & 1) * 32;            // 2 M groups
    int n0  = (wid >> 1) * 24;           // 4 N groups

    int row0 = blockIdx.x * NTILE;
    const uint32_t* aggr_u = reinterpret_cast<const uint32_t*>(g_aggr);

    // async fill A tile: 64 rows x 24 float4
    for (int i = t; i < NTILE * (D / 4); i += 256) {
        int r = i / (D / 4), c4 = i % (D / 4);
        int gr = row0 + r;
        const uint32_t* src = aggr_u + (size_t)gr * D + c4 * 4;
        uint32_t dst = sA_b + (uint32_t)(r * LDP + c4 * 4) * 4u;
        int sz = (gr < N) ? 16 : 0;
        asm volatile("cp.async.cg.shared.global [%0], [%1], 16, %2;"
                     :: "r"(dst), "l"(src), "r"(sz));
    }
    // async fill W tile: 96 rows x 24 float4
    for (int i = t; i < D * (D / 4); i += 256) {
        int r = i / (D / 4), c4 = i % (D / 4);
        const uint32_t* src = g_wt + (size_t)r * D + c4 * 4;
        uint32_t dst = sW_b + (uint32_t)(r * LDP + c4 * 4) * 4u;
        asm volatile("cp.async.cg.shared.global [%0], [%1], 16;"
                     :: "r"(dst), "l"(src));
    }
    asm volatile("cp.async.commit_group;");
    asm volatile("cp.async.wait_group 0;");
    __syncthreads();

    float c[2][3][4];
#pragma unroll
    for (int mt = 0; mt < 2; mt++)
#pragma unroll
        for (int nt = 0; nt < 3; nt++)
#pragma unroll
            for (int q = 0; q < 4; q++) c[mt][nt][q] = 0.f;

    int arow = lid >> 2;                 // 0..7
    int acol = lid & 3;                  // 0..3

#pragma unroll
    for (int ks = 0; ks < 12; ks++) {
        int k0 = ks * 8;

        uint32_t a[2][4];
#pragma unroll
        for (int mt = 0; mt < 2; mt++) {
            const uint32_t* base = sA + (m0 + mt * 16 + arow) * LDP + k0 + acol;
            a[mt][0] = base[0];
            a[mt][1] = base[8 * LDP];
            a[mt][2] = base[4];
            a[mt][3] = base[8 * LDP + 4];
        }
        uint32_t bfr[3][2];
#pragma unroll
        for (int nt = 0; nt < 3; nt++) {
            const uint32_t* base = sW + (n0 + nt * 8 + arow) * LDP + k0 + acol;
            bfr[nt][0] = base[0];
            bfr[nt][1] = base[4];
        }

#pragma unroll
        for (int mt = 0; mt < 2; mt++)
#pragma unroll
            for (int nt = 0; nt < 3; nt++) {
                asm volatile(
                    "mma.sync.aligned.m16n8k8.row.col.f32.tf32.tf32.f32 "
                    "{%0,%1,%2,%3}, {%4,%5,%6,%7}, {%8,%9}, {%0,%1,%2,%3};"
                    : "+f"(c[mt][nt][0]), "+f"(c[mt][nt][1]),
                      "+f"(c[mt][nt][2]), "+f"(c[mt][nt][3])
                    : "r"(a[mt][0]), "r"(a[mt][1]), "r"(a[mt][2]), "r"(a[mt][3]),
                      "r"(bfr[nt][0]), "r"(bfr[nt][1]));
            }
    }

    // epilogue: c0,c1 -> (row, 2c),(row, 2c+1); c2,c3 -> row+8
#pragma unroll
    for (int nt = 0; nt < 3; nt++) {
        int col = n0 + nt * 8 + 2 * acol;
        float b0 = __ldg(bias + col);
        float b1 = __ldg(bias + col + 1);
#pragma unroll
        for (int mt = 0; mt < 2; mt++) {
            int r_lo = row0 + m0 + mt * 16 + arow;
            if (r_lo < N) {
                float2 v = make_float2(c[mt][nt][0] + b0, c[mt][nt][1] + b1);
                *reinterpret_cast<float2*>(out + (size_t)r_lo * D + col) = v;
            }
            int r_hi = r_lo + 8;
            if (r_hi < N) {
                float2 v = make_float2(c[mt][nt][2] + b0, c[mt][nt][3] + b1);
                *reinterpret_cast<float2*>(out + (size_t)r_hi * D + col) = v;
            }
        }
    }
}

// ---------------------------------------------------------------------------
// Launch. Inputs: x[N*D] f32, edge_index[2*E] i32, edge_weight[E] f32,
//                 pagerank[N] f32, W[D*D] f32, b[D] f32. Output f32 [N,D].
// ---------------------------------------------------------------------------
extern "C" void kernel_launch(void* const* d_in, const int* in_sizes, int n_in,
                              void* d_out, int out_size) {
    const float* x  = (const float*)d_in[0];
    const int*   ei = (const int*)  d_in[1];
    const float* ew = (const float*)d_in[2];
    const float* pr = (const float*)d_in[3];
    const float* Wm = (const float*)d_in[4];
    const float* b  = (const float*)d_in[5];
    float* out = (float*)d_out;

    int N = in_sizes[0] / D;
    int E = in_sizes[1] / 2;

    const int gemm_smem = (NTILE * LDP + D * LDP) * (int)sizeof(uint32_t);
    cudaFuncSetAttribute(mma_gemm_kernel,
                         cudaFuncAttributeMaxDynamicSharedMemorySize, gemm_smem);

    int nthread = (E + EPT - 1) / EPT;
    bucket_kernel<<<(nthread + 255) / 256, 256>>>(ei, ew, pr, Wm, E);

    int agg_blocks = (N + 7) / 8;
    aggregate_kernel<<<agg_blocks, 256>>>(x, N, agg_blocks * 8);

    mma_gemm_kernel<<<(N + NTILE - 1) / NTILE, 256, gemm_smem>>>(b, out, N);
}

// round 13
// speedup vs baseline: 1.9105x; 1.3970x over previous
#include <cuda_runtime.h>
#include <cstdint>

#define D 96
#define MAX_N 50000
#define MAXDEG 64
#define MAX_OVF 4096

// ---- scratch (static device globals; no allocation) -----------------------
__device__ float    g_aggr[MAX_N * D];          // tf32-rounded aggr + x
__device__ uint32_t g_wt[D * D];                // tf32-rounded W bits
__device__ int      g_cnt[MAX_N];               // per-node cursor / degree
__device__ int2     g_pack[MAX_N * MAXDEG];     // (src, bitcast(w)) buckets
__device__ int      g_ovfcnt;
__device__ int4     g_ovf[MAX_OVF];             // (src, dst, bitcast(w), pad)

__device__ __forceinline__ float to_tf32(float x) {
    float r;
    asm("cvt.rna.tf32.f32 %0, %1;" : "=f"(r) : "f"(x));
    return r;
}
__device__ __forceinline__ uint32_t smem_u32(const void* p) {
    uint32_t a;
    asm("{ .reg .u64 t; cvta.to.shared.u64 t, %1; cvt.u32.u64 %0, t; }"
        : "=r"(a) : "l"(p));
    return a;
}

// ---------------------------------------------------------------------------
// K1: zero cursors + overflow counter, AND pre-convert W to tf32 bits.
// ---------------------------------------------------------------------------
__global__ void zero_wconv_kernel(const float* __restrict__ Wm, int N) {
    int i = blockIdx.x * blockDim.x + threadIdx.x;
    if (i < N) g_cnt[i] = 0;
    if (i == 0) g_ovfcnt = 0;
    if (i < D * D) {
        uint32_t u;
        asm("cvt.rna.tf32.f32 %0, %1;" : "=r"(u) : "f"(__ldg(Wm + i)));
        g_wt[i] = u;
    }
}

// ---------------------------------------------------------------------------
// K2: bucket edges. 4 edges per thread (measured best: atomic-latency bound,
// wants high occupancy; low regs).
// ---------------------------------------------------------------------------
#define EPT 4
__global__ void bucket_kernel(const int* __restrict__ ei,
                              const float* __restrict__ ew,
                              const float* __restrict__ pr,
                              int E) {
    int base = (blockIdx.x * blockDim.x + threadIdx.x) * EPT;
    int src[EPT], dst[EPT];
    float w[EPT];
#pragma unroll
    for (int u = 0; u < EPT; u++) {
        int e = base + u;
        if (e < E) { src[u] = __ldg(ei + e); dst[u] = __ldg(ei + E + e); w[u] = __ldg(ew + e); }
    }
#pragma unroll
    for (int u = 0; u < EPT; u++) {
        int e = base + u;
        if (e < E) w[u] *= __ldg(pr + src[u]);
    }
#pragma unroll
    for (int u = 0; u < EPT; u++) {
        int e = base + u;
        if (e < E) {
            int pos = atomicAdd(&g_cnt[dst[u]], 1);
            if (pos < MAXDEG) {
                g_pack[dst[u] * MAXDEG + pos] = make_int2(src[u], __float_as_int(w[u]));
            } else {
                int o = atomicAdd(&g_ovfcnt, 1);
                if (o < MAX_OVF)
                    g_ovf[o] = make_int4(src[u], dst[u], __float_as_int(w[u]), 0);
            }
        }
    }
}

// ---------------------------------------------------------------------------
// K3: per-node aggregation (R8 form). One warp per node; residual +x folded.
// Pack list staged to smem; gather loop unrolled x4 (12 loads in flight).
// Output written tf32-rounded so GEMM fill is a raw async copy.
// ---------------------------------------------------------------------------
__global__ void aggregate_kernel(const float* __restrict__ x, int N) {
    __shared__ int2 s_pack[8][MAXDEG];

    int wid  = threadIdx.x >> 5;
    int l    = threadIdx.x & 31;
    int node = blockIdx.x * 8 + wid;
    if (node >= N) return;

    int cnt = g_cnt[node];
    if (cnt > MAXDEG) cnt = MAXDEG;

    const int2* bucket = g_pack + (size_t)node * MAXDEG;
    for (int k = l; k < cnt; k += 32)
        s_pack[wid][k] = __ldg(bucket + k);
    __syncwarp();

    const float* xr0 = x + (size_t)node * D;
    float a0 = __ldg(xr0 + l);
    float a1 = __ldg(xr0 + 32 + l);
    float a2 = __ldg(xr0 + 64 + l);

    int j = 0;
    for (; j + 4 <= cnt; j += 4) {
        int   s[4]; float w[4];
#pragma unroll
        for (int u = 0; u < 4; u++) {
            int2 p = s_pack[wid][j + u];
            s[u] = p.x; w[u] = __int_as_float(p.y);
        }
        float b0[4], b1[4], b2[4];
#pragma unroll
        for (int u = 0; u < 4; u++) {
            const float* xr = x + (size_t)s[u] * D;
            b0[u] = __ldg(xr + l);
            b1[u] = __ldg(xr + 32 + l);
            b2[u] = __ldg(xr + 64 + l);
        }
#pragma unroll
        for (int u = 0; u < 4; u++) {
            a0 += w[u] * b0[u];
            a1 += w[u] * b1[u];
            a2 += w[u] * b2[u];
        }
    }
    for (; j < cnt; j++) {
        int2 p = s_pack[wid][j];
        float w = __int_as_float(p.y);
        const float* xr = x + (size_t)p.x * D;
        a0 += w * __ldg(xr + l);
        a1 += w * __ldg(xr + 32 + l);
        a2 += w * __ldg(xr + 64 + l);
    }

    int ovf = g_ovfcnt;
    if (ovf > 0) {
        if (ovf > MAX_OVF) ovf = MAX_OVF;
        for (int i = 0; i < ovf; i++) {
            int4 p = g_ovf[i];
            if (p.y == node) {
                float w = __int_as_float(p.z);
                const float* xr = x + (size_t)p.x * D;
                a0 += w * __ldg(xr + l);
                a1 += w * __ldg(xr + 32 + l);
                a2 += w * __ldg(xr + 64 + l);
            }
        }
    }

    float* o = g_aggr + (size_t)node * D;
    o[l]      = to_tf32(a0);
    o[32 + l] = to_tf32(a1);
    o[64 + l] = to_tf32(a2);
}

// ---------------------------------------------------------------------------
// K4: tf32 mma.sync GEMM — grid-strided, double-buffered multi-tile.
// Each of 296 CTAs loads W ONCE, then loops over 64-node tiles with a 2-deep
// cp.async A-buffer pipeline: tile t+stride prefetches while t computes.
// 8 warps = 2 M-groups (32 rows) x 4 N-groups (24 cols); warp tile 2m16 x 3n8.
// smem = W 38.4KB + 2 x A 25.6KB = 89.6KB -> 2 CTAs/SM (no reg cap: lb(256,2)).
// LDP=100 pad keeps every fragment LDS conflict-free.
// ---------------------------------------------------------------------------
#define LDP 100
#define NTILE 64
__global__ __launch_bounds__(256, 2)
void mma_gemm_kernel(const float* __restrict__ bias,
                     float* __restrict__ out,
                     int N, int ntiles) {
    extern __shared__ uint32_t smem[];
    uint32_t* sW = smem;                     // [96][LDP]
    uint32_t* sA0 = smem + D * LDP;          // [64][LDP] buffer 0
    uint32_t* sA1 = sA0 + NTILE * LDP;       // [64][LDP] buffer 1
    uint32_t sW_b  = smem_u32(sW);
    uint32_t sA0_b = smem_u32(sA0);
    uint32_t sA1_b = smem_u32(sA1);

    int t   = threadIdx.x;                   // 0..255
    int lid = t & 31;
    int wid = t >> 5;                        // 0..7
    int m0  = (wid & 1) * 32;                // 2 M groups
    int n0  = (wid >> 1) * 24;               // 4 N groups
    int arow = lid >> 2;                     // 0..7
    int acol = lid & 3;                      // 0..3

    const uint32_t* aggr_u = reinterpret_cast<const uint32_t*>(g_aggr);
    int stride = gridDim.x;

    // issue an A-tile fill into the given buffer (async, uncommitted)
    auto fill_A = [&](int tile, uint32_t buf_b) {
        int row0 = tile * NTILE;
        for (int i = t; i < NTILE * (D / 4); i += 256) {
            int r = i / (D / 4), c4 = i % (D / 4);
            int gr = row0 + r;
            const uint32_t* src = aggr_u + (size_t)gr * D + c4 * 4;
            uint32_t dst = buf_b + (uint32_t)(r * LDP + c4 * 4) * 4u;
            int sz = (gr < N) ? 16 : 0;
            asm volatile("cp.async.cg.shared.global [%0], [%1], 16, %2;"
                         :: "r"(dst), "l"(src), "r"(sz));
        }
    };

    // W fill (once) + first A tile, one commit group
    for (int i = t; i < D * (D / 4); i += 256) {
        int r = i / (D / 4), c4 = i % (D / 4);
        const uint32_t* src = g_wt + (size_t)r * D + c4 * 4;
        uint32_t dst = sW_b + (uint32_t)(r * LDP + c4 * 4) * 4u;
        asm volatile("cp.async.cg.shared.global [%0], [%1], 16;"
                     :: "r"(dst), "l"(src));
    }
    int tile0 = blockIdx.x;
    if (tile0 < ntiles) fill_A(tile0, sA0_b);
    asm volatile("cp.async.commit_group;");

    int pipe = 0;
    for (int tile = tile0; tile < ntiles; tile += stride) {
        uint32_t* sA = pipe ? sA1 : sA0;

        // wait for this tile's buffer (and W on the first pass)
        asm volatile("cp.async.wait_group 0;");
        __syncthreads();

        // prefetch next tile into the other buffer
        int next = tile + stride;
        if (next < ntiles) {
            fill_A(next, pipe ? sA0_b : sA1_b);
        }
        asm volatile("cp.async.commit_group;");

        int row0 = tile * NTILE;

        float c[2][3][4];
#pragma unroll
        for (int mt = 0; mt < 2; mt++)
#pragma unroll
            for (int nt = 0; nt < 3; nt++)
#pragma unroll
                for (int q = 0; q < 4; q++) c[mt][nt][q] = 0.f;

#pragma unroll
        for (int ks = 0; ks < 12; ks++) {
            int k0 = ks * 8;

            uint32_t a[2][4];
#pragma unroll
            for (int mt = 0; mt < 2; mt++) {
                const uint32_t* base = sA + (m0 + mt * 16 + arow) * LDP + k0 + acol;
                a[mt][0] = base[0];
                a[mt][1] = base[8 * LDP];
                a[mt][2] = base[4];
                a[mt][3] = base[8 * LDP + 4];
            }
            uint32_t bfr[3][2];
#pragma unroll
            for (int nt = 0; nt < 3; nt++) {
                const uint32_t* base = sW + (n0 + nt * 8 + arow) * LDP + k0 + acol;
                bfr[nt][0] = base[0];
                bfr[nt][1] = base[4];
            }

#pragma unroll
            for (int mt = 0; mt < 2; mt++)
#pragma unroll
                for (int nt = 0; nt < 3; nt++) {
                    asm volatile(
                        "mma.sync.aligned.m16n8k8.row.col.f32.tf32.tf32.f32 "
                        "{%0,%1,%2,%3}, {%4,%5,%6,%7}, {%8,%9}, {%0,%1,%2,%3};"
                        : "+f"(c[mt][nt][0]), "+f"(c[mt][nt][1]),
                          "+f"(c[mt][nt][2]), "+f"(c[mt][nt][3])
                        : "r"(a[mt][0]), "r"(a[mt][1]), "r"(a[mt][2]), "r"(a[mt][3]),
                          "r"(bfr[nt][0]), "r"(bfr[nt][1]));
                }
        }

        // epilogue: c0,c1 -> (row, 2c),(row, 2c+1); c2,c3 -> row+8
#pragma unroll
        for (int nt = 0; nt < 3; nt++) {
            int col = n0 + nt * 8 + 2 * acol;
            float b0 = __ldg(bias + col);
            float b1 = __ldg(bias + col + 1);
#pragma unroll
            for (int mt = 0; mt < 2; mt++) {
                int r_lo = row0 + m0 + mt * 16 + arow;
                if (r_lo < N) {
                    float2 v = make_float2(c[mt][nt][0] + b0, c[mt][nt][1] + b1);
                    *reinterpret_cast<float2*>(out + (size_t)r_lo * D + col) = v;
                }
                int r_hi = r_lo + 8;
                if (r_hi < N) {
                    float2 v = make_float2(c[mt][nt][2] + b0, c[mt][nt][3] + b1);
                    *reinterpret_cast<float2*>(out + (size_t)r_hi * D + col) = v;
                }
            }
        }

        // all warps done reading this buffer before it is refilled next iter
        __syncthreads();
        pipe ^= 1;
    }
}

// ---------------------------------------------------------------------------
// Launch. Inputs: x[N*D] f32, edge_index[2*E] i32, edge_weight[E] f32,
//                 pagerank[N] f32, W[D*D] f32, b[D] f32. Output f32 [N,D].
// ---------------------------------------------------------------------------
extern "C" void kernel_launch(void* const* d_in, const int* in_sizes, int n_in,
                              void* d_out, int out_size) {
    const float* x  = (const float*)d_in[0];
    const int*   ei = (const int*)  d_in[1];
    const float* ew = (const float*)d_in[2];
    const float* pr = (const float*)d_in[3];
    const float* Wm = (const float*)d_in[4];
    const float* b  = (const float*)d_in[5];
    float* out = (float*)d_out;

    int N = in_sizes[0] / D;
    int E = in_sizes[1] / 2;

    const int gemm_smem = (D * LDP + 2 * NTILE * LDP) * (int)sizeof(uint32_t);
    cudaFuncSetAttribute(mma_gemm_kernel,
                         cudaFuncAttributeMaxDynamicSharedMemorySize, gemm_smem);

    zero_wconv_kernel<<<(N + 255) / 256, 256>>>(Wm, N);

    int nthread = (E + EPT - 1) / EPT;
    bucket_kernel<<<(nthread + 255) / 256, 256>>>(ei, ew, pr, E);

    aggregate_kernel<<<(N + 7) / 8, 256>>>(x, N);

    int ntiles = (N + NTILE - 1) / NTILE;
    int grid = 296;                       // 2 x 148 SMs
    if (grid > ntiles) grid = ntiles;
    mma_gemm_kernel<<<grid, 256, gemm_smem>>>(b, out, N, ntiles);
}